// round 3
// baseline (speedup 1.0000x reference)
#include <cuda_runtime.h>
#include <math.h>

#define HH 512
#define WW 512
#define BN 32
#define CN 3

// Scratch (allocation-free rule: __device__ globals)
__device__ float g_Minv[BN * 9];
__device__ float g_A[HH * WW];          // L * 0.85
__device__ float g_Z[CN * HH * WW];     // min(z1,z2) * 0.15

// ---------------------------------------------------------------------------
// Closed-form homography (Heckbert square->quad) + 3x3 inverse, fp64.
// ---------------------------------------------------------------------------
__device__ __forceinline__ void solve_one(int b, const float* __restrict__ dst_off) {
    const double bu[4] = {0.0, 512.0, 512.0, 0.0};
    const double bv[4] = {0.0, 0.0, 512.0, 512.0};
    double u[4], v[4];
    #pragma unroll
    for (int i = 0; i < 4; i++) {
        u[i] = bu[i] + (double)dst_off[(b * 4 + i) * 2 + 0];
        v[i] = bv[i] + (double)dst_off[(b * 4 + i) * 2 + 1];
    }
    double sx  = u[0] - u[1] + u[2] - u[3];
    double sy  = v[0] - v[1] + v[2] - v[3];
    double dx1 = u[1] - u[2], dx2 = u[3] - u[2];
    double dy1 = v[1] - v[2], dy2 = v[3] - v[2];
    double den = dx1 * dy2 - dx2 * dy1;
    double g = (sx * dy2 - dx2 * sy) / den;
    double h = (dx1 * sy - sx * dy1) / den;
    double a = u[1] - u[0] + g * u[1];
    double bb = u[3] - u[0] + h * u[3];
    double c = u[0];
    double d = v[1] - v[0] + g * v[1];
    double e = v[3] - v[0] + h * v[3];
    double f = v[0];
    const double is = 1.0 / 511.0;
    double m[9] = {a * is, bb * is, c,
                   d * is, e  * is, f,
                   g * is, h  * is, 1.0};

    double det = m[0] * (m[4] * m[8] - m[5] * m[7])
               - m[1] * (m[3] * m[8] - m[5] * m[6])
               + m[2] * (m[3] * m[7] - m[4] * m[6]);
    double id = 1.0 / det;

    float* o = g_Minv + b * 9;
    o[0] = (float)( (m[4] * m[8] - m[5] * m[7]) * id);
    o[1] = (float)(-(m[1] * m[8] - m[2] * m[7]) * id);
    o[2] = (float)( (m[1] * m[5] - m[2] * m[4]) * id);
    o[3] = (float)(-(m[3] * m[8] - m[5] * m[6]) * id);
    o[4] = (float)( (m[0] * m[8] - m[2] * m[6]) * id);
    o[5] = (float)(-(m[0] * m[5] - m[2] * m[3]) * id);
    o[6] = (float)( (m[3] * m[7] - m[4] * m[6]) * id);
    o[7] = (float)(-(m[0] * m[7] - m[1] * m[6]) * id);
    o[8] = (float)( (m[0] * m[4] - m[1] * m[3]) * id);
}

// ---------------------------------------------------------------------------
// Fused setup: light mask (x0.85) + moire (x0.15) + per-batch homographies.
// cos(2*pi*t) is periodic in t with period 1 -> reduce t mod 1 and use the
// MUFU fast path (__cosf), accurate to ~2^-21 on the reduced argument.
// ---------------------------------------------------------------------------
__global__ void setup_kernel(const float* __restrict__ dst_off,
                             const float* __restrict__ ab,
                             const float* __restrict__ centers,
                             const int* __restrict__ cflag,
                             const int* __restrict__ direction,
                             const int* __restrict__ light_xy,
                             const int* __restrict__ theta) {
    if (blockIdx.x == gridDim.x - 1) {
        int b = threadIdx.x;
        if (b < BN) solve_one(b, dst_off);
        return;
    }
    int idx = blockIdx.x * blockDim.x + threadIdx.x;
    int i = idx / WW;   // row
    int j = idx % WW;   // col

    float a = ab[0], bb = ab[1];
    float L;
    if (cflag[0] == 0) {
        int k = direction[0] - 1;  // rot90 count {0,1,2,3}
        int t = (k == 0) ? i : (k == 1) ? j : (k == 2) ? (HH - 1 - i) : (WW - 1 - j);
        L = -((bb - a) / (float)(HH - 1)) * ((float)t - (float)WW) + a;
    } else {
        float x = (float)light_xy[0], y = (float)light_xy[1];
        float d0 = sqrtf(x * x + y * y);
        float d1 = sqrtf((x - 255.f) * (x - 255.f) + y * y);
        float d2 = sqrtf(x * x + (y - 255.f) * (y - 255.f));
        float d3 = sqrtf((x - 512.f) * (x - 512.f) + (y - 512.f) * (y - 512.f));
        float ml = fmaxf(fmaxf(d0, d1), fmaxf(d2, d3));
        float dx = (float)i - x, dy = (float)j - y;
        float dist = sqrtf(dx * dx + dy * dy);
        L = dist / ml * (a - bb) + bb;
    }
    g_A[idx] = L * 0.85f;

    const float TWO_PI = 6.283185307179586f;
    float xg = (float)(i + 1), yg = (float)(j + 1);
    #pragma unroll
    for (int k = 0; k < 3; k++) {
        float cx = centers[k * 2 + 0], cy = centers[k * 2 + 1];
        float th = (float)theta[k] * 0.017453292519943295f;
        float cth, sth;
        sincosf(th, &sth, &cth);
        float dx = xg - cx, dy = yg - cy;
        float dist = sqrtf(dx * dx + dy * dy);
        float f1 = dist - floorf(dist);                 // mod 1 (period of cos(2*pi*t))
        float t2 = cth * xg + sth * yg;
        float f2 = t2 - floorf(t2);
        float z1 = 0.5f + 0.5f * __cosf(TWO_PI * f1);
        float z2 = 0.5f + 0.5f * __cosf(TWO_PI * f2);
        g_Z[k * (HH * WW) + idx] = fminf(z1, z2) * 0.15f;
    }
}

// ---------------------------------------------------------------------------
// Fused warp + blend. Block = 128 threads handles one (b, y) row of 512 px.
// Iteration p: x = p*128 + lane  -> consecutive lanes hit consecutive source
// columns, so every bilinear-tap LDG is ~1 L1 wavefront (vs 4 with
// pixel-per-thread packing).
// ---------------------------------------------------------------------------
__global__ void __launch_bounds__(128) main_kernel(const float* __restrict__ img,
                                                   const float* __restrict__ noise,
                                                   float* __restrict__ out) {
    int b = blockIdx.z;
    int y = blockIdx.y;
    int tid = threadIdx.x;

    const float* Mi = g_Minv + b * 9;
    float m00 = Mi[0], m01 = Mi[1], m02 = Mi[2];
    float m10 = Mi[3], m11 = Mi[4], m12 = Mi[5];
    float m20 = Mi[6], m21 = Mi[7], m22 = Mi[8];
    float fy = (float)y;
    // fold the fy terms once
    float c0 = m01 * fy + m02;
    float c1 = m11 * fy + m12;
    float c2 = m21 * fy + m22;

    const float kn = 0.031622776601683794f;  // sqrt(0.001)
    const size_t rowbase = (size_t)y * WW;

    #pragma unroll
    for (int p = 0; p < 4; p++) {
        int x = p * 128 + tid;
        float fx = (float)x;
        float inv = 1.0f / (m20 * fx + c2);
        float xs = (m00 * fx + c0) * inv;
        float ys = (m10 * fx + c1) * inv;
        float xf = floorf(xs), yf = floorf(ys);
        float wx = xs - xf, wy = ys - yf;
        int ix = (int)xf, iy = (int)yf;
        bool vx0 = (ix >= 0) && (ix < WW);
        bool vx1 = (ix + 1 >= 0) && (ix + 1 < WW);
        bool vy0 = (iy >= 0) && (iy < HH);
        bool vy1 = (iy + 1 >= 0) && (iy + 1 < HH);
        int cx0 = min(max(ix, 0), WW - 1), cx1 = min(max(ix + 1, 0), WW - 1);
        int cy0 = min(max(iy, 0), HH - 1), cy1 = min(max(iy + 1, 0), HH - 1);
        float w00 = (1.f - wx) * (1.f - wy);
        float w01 = wx * (1.f - wy);
        float w10 = (1.f - wx) * wy;
        float w11 = wx * wy;

        float res[3];
        #pragma unroll
        for (int ch = 0; ch < 3; ch++) {
            const float* base = img + (size_t)(b * 3 + ch) * (HH * WW);
            float v00 = (vx0 && vy0) ? __ldg(base + cy0 * WW + cx0) : 0.f;
            float v01 = (vx1 && vy0) ? __ldg(base + cy0 * WW + cx1) : 0.f;
            float v10 = (vx0 && vy1) ? __ldg(base + cy1 * WW + cx0) : 0.f;
            float v11 = (vx1 && vy1) ? __ldg(base + cy1 * WW + cx1) : 0.f;
            res[ch] = v00 * w00 + v01 * w01 + v10 * w10 + v11 * w11;
        }

        float Av = __ldg(g_A + rowbase + x);
        #pragma unroll
        for (int ch = 0; ch < 3; ch++) {
            size_t off = ((size_t)(b * 3 + ch) * HH + y) * WW + x;
            float nv = __ldg(noise + off);
            float zv = __ldg(g_Z + (ch * HH + y) * WW + x);
            out[off] = res[ch] * Av + zv + kn * nv;
        }
    }
}

// ---------------------------------------------------------------------------
extern "C" void kernel_launch(void* const* d_in, const int* in_sizes, int n_in,
                              void* d_out, int out_size) {
    const float* image    = (const float*)d_in[0];
    const float* dst_off  = (const float*)d_in[1];
    const float* ab       = (const float*)d_in[2];
    const float* centers  = (const float*)d_in[3];
    const float* noise    = (const float*)d_in[4];
    const int*   c        = (const int*)d_in[5];
    const int*   direction= (const int*)d_in[6];
    const int*   light_xy = (const int*)d_in[7];
    const int*   theta    = (const int*)d_in[8];
    float* out = (float*)d_out;

    setup_kernel<<<(HH * WW) / 256 + 1, 256>>>(dst_off, ab, centers, c,
                                               direction, light_xy, theta);
    dim3 grid(1, HH, BN);
    main_kernel<<<grid, 128>>>(image, noise, out);
}

// round 4
// speedup vs baseline: 1.0761x; 1.0761x over previous
#include <cuda_runtime.h>
#include <math.h>

#define HH 512
#define WW 512
#define BN 32
#define CN 3

// Scratch (allocation-free rule: __device__ globals)
__device__ float g_Minv[BN * 9];
__device__ float g_A[HH * WW];          // L * 0.85
__device__ float g_Z[CN * HH * WW];     // min(z1,z2) * 0.15

// ---------------------------------------------------------------------------
// Closed-form homography (Heckbert square->quad) + 3x3 inverse, fp64.
// ---------------------------------------------------------------------------
__device__ __forceinline__ void solve_one(int b, const float* __restrict__ dst_off) {
    const double bu[4] = {0.0, 512.0, 512.0, 0.0};
    const double bv[4] = {0.0, 0.0, 512.0, 512.0};
    double u[4], v[4];
    #pragma unroll
    for (int i = 0; i < 4; i++) {
        u[i] = bu[i] + (double)dst_off[(b * 4 + i) * 2 + 0];
        v[i] = bv[i] + (double)dst_off[(b * 4 + i) * 2 + 1];
    }
    double sx  = u[0] - u[1] + u[2] - u[3];
    double sy  = v[0] - v[1] + v[2] - v[3];
    double dx1 = u[1] - u[2], dx2 = u[3] - u[2];
    double dy1 = v[1] - v[2], dy2 = v[3] - v[2];
    double den = dx1 * dy2 - dx2 * dy1;
    double g = (sx * dy2 - dx2 * sy) / den;
    double h = (dx1 * sy - sx * dy1) / den;
    double a = u[1] - u[0] + g * u[1];
    double bb = u[3] - u[0] + h * u[3];
    double c = u[0];
    double d = v[1] - v[0] + g * v[1];
    double e = v[3] - v[0] + h * v[3];
    double f = v[0];
    const double is = 1.0 / 511.0;
    double m[9] = {a * is, bb * is, c,
                   d * is, e  * is, f,
                   g * is, h  * is, 1.0};

    double det = m[0] * (m[4] * m[8] - m[5] * m[7])
               - m[1] * (m[3] * m[8] - m[5] * m[6])
               + m[2] * (m[3] * m[7] - m[4] * m[6]);
    double id = 1.0 / det;

    float* o = g_Minv + b * 9;
    o[0] = (float)( (m[4] * m[8] - m[5] * m[7]) * id);
    o[1] = (float)(-(m[1] * m[8] - m[2] * m[7]) * id);
    o[2] = (float)( (m[1] * m[5] - m[2] * m[4]) * id);
    o[3] = (float)(-(m[3] * m[8] - m[5] * m[6]) * id);
    o[4] = (float)( (m[0] * m[8] - m[2] * m[6]) * id);
    o[5] = (float)(-(m[0] * m[5] - m[2] * m[3]) * id);
    o[6] = (float)( (m[3] * m[7] - m[4] * m[6]) * id);
    o[7] = (float)(-(m[0] * m[7] - m[1] * m[6]) * id);
    o[8] = (float)( (m[0] * m[4] - m[1] * m[3]) * id);
}

// ---------------------------------------------------------------------------
// Fused setup: light mask (x0.85) + moire (x0.15) + per-batch homographies.
// ---------------------------------------------------------------------------
__global__ void setup_kernel(const float* __restrict__ dst_off,
                             const float* __restrict__ ab,
                             const float* __restrict__ centers,
                             const int* __restrict__ cflag,
                             const int* __restrict__ direction,
                             const int* __restrict__ light_xy,
                             const int* __restrict__ theta) {
    if (blockIdx.x == gridDim.x - 1) {
        int b = threadIdx.x;
        if (b < BN) solve_one(b, dst_off);
        return;
    }
    int idx = blockIdx.x * blockDim.x + threadIdx.x;
    int i = idx / WW;   // row
    int j = idx % WW;   // col

    float a = ab[0], bb = ab[1];
    float L;
    if (cflag[0] == 0) {
        int k = direction[0] - 1;  // rot90 count {0,1,2,3}
        int t = (k == 0) ? i : (k == 1) ? j : (k == 2) ? (HH - 1 - i) : (WW - 1 - j);
        L = -((bb - a) / (float)(HH - 1)) * ((float)t - (float)WW) + a;
    } else {
        float x = (float)light_xy[0], y = (float)light_xy[1];
        float d0 = sqrtf(x * x + y * y);
        float d1 = sqrtf((x - 255.f) * (x - 255.f) + y * y);
        float d2 = sqrtf(x * x + (y - 255.f) * (y - 255.f));
        float d3 = sqrtf((x - 512.f) * (x - 512.f) + (y - 512.f) * (y - 512.f));
        float ml = fmaxf(fmaxf(d0, d1), fmaxf(d2, d3));
        float dx = (float)i - x, dy = (float)j - y;
        float dist = sqrtf(dx * dx + dy * dy);
        L = dist / ml * (a - bb) + bb;
    }
    g_A[idx] = L * 0.85f;

    const float TWO_PI = 6.283185307179586f;
    float xg = (float)(i + 1), yg = (float)(j + 1);
    #pragma unroll
    for (int k = 0; k < 3; k++) {
        float cx = centers[k * 2 + 0], cy = centers[k * 2 + 1];
        float th = (float)theta[k] * 0.017453292519943295f;
        float cth, sth;
        sincosf(th, &sth, &cth);
        float dx = xg - cx, dy = yg - cy;
        float dist = sqrtf(dx * dx + dy * dy);
        float f1 = dist - floorf(dist);                 // period-1 reduction
        float t2 = cth * xg + sth * yg;
        float f2 = t2 - floorf(t2);
        float z1 = 0.5f + 0.5f * __cosf(TWO_PI * f1);
        float z2 = 0.5f + 0.5f * __cosf(TWO_PI * f2);
        g_Z[k * (HH * WW) + idx] = fminf(z1, z2) * 0.15f;
    }
}

// ---------------------------------------------------------------------------
// Fused warp + blend. Block = 128 threads = one (b, y) output row.
// Phase 1: gather with lane-consecutive source columns (x = p*128 + lane)
//          -> each bilinear tap is ~1 L1 wavefront; result goes to smem.
// Phase 2: re-lane via smem so noise/Z/A/out are float4 (x = 4*lane + i).
// ---------------------------------------------------------------------------
__global__ void __launch_bounds__(128) main_kernel(const float* __restrict__ img,
                                                   const float* __restrict__ noise,
                                                   float* __restrict__ out) {
    __shared__ float sres[3][WW];

    int b = blockIdx.z;
    int y = blockIdx.y;
    int tid = threadIdx.x;

    const float* Mi = g_Minv + b * 9;
    float m00 = Mi[0], m01 = Mi[1], m02 = Mi[2];
    float m10 = Mi[3], m11 = Mi[4], m12 = Mi[5];
    float m20 = Mi[6], m21 = Mi[7], m22 = Mi[8];
    float fy = (float)y;
    float c0 = m01 * fy + m02;
    float c1 = m11 * fy + m12;
    float c2 = m21 * fy + m22;

    #pragma unroll
    for (int p = 0; p < 4; p++) {
        int x = p * 128 + tid;
        float fx = (float)x;
        float inv = 1.0f / (m20 * fx + c2);
        float xs = (m00 * fx + c0) * inv;
        float ys = (m10 * fx + c1) * inv;
        float xf = floorf(xs), yf = floorf(ys);
        float wx = xs - xf, wy = ys - yf;
        int ix = (int)xf, iy = (int)yf;
        bool vx0 = (ix >= 0) && (ix < WW);
        bool vx1 = (ix + 1 >= 0) && (ix + 1 < WW);
        bool vy0 = (iy >= 0) && (iy < HH);
        bool vy1 = (iy + 1 >= 0) && (iy + 1 < HH);
        int cx0 = min(max(ix, 0), WW - 1), cx1 = min(max(ix + 1, 0), WW - 1);
        int cy0 = min(max(iy, 0), HH - 1), cy1 = min(max(iy + 1, 0), HH - 1);
        float w00 = (1.f - wx) * (1.f - wy);
        float w01 = wx * (1.f - wy);
        float w10 = (1.f - wx) * wy;
        float w11 = wx * wy;

        #pragma unroll
        for (int ch = 0; ch < 3; ch++) {
            const float* base = img + (size_t)(b * 3 + ch) * (HH * WW);
            float v00 = (vx0 && vy0) ? __ldg(base + cy0 * WW + cx0) : 0.f;
            float v01 = (vx1 && vy0) ? __ldg(base + cy0 * WW + cx1) : 0.f;
            float v10 = (vx0 && vy1) ? __ldg(base + cy1 * WW + cx0) : 0.f;
            float v11 = (vx1 && vy1) ? __ldg(base + cy1 * WW + cx1) : 0.f;
            sres[ch][x] = v00 * w00 + v01 * w01 + v10 * w10 + v11 * w11;
        }
    }

    __syncthreads();

    // Phase 2: vectorized blend. Thread t -> pixels [4t, 4t+4).
    const float kn = 0.031622776601683794f;  // sqrt(0.001)
    int x0 = tid * 4;
    float4 av = *(const float4*)(g_A + (size_t)y * WW + x0);

    #pragma unroll
    for (int ch = 0; ch < 3; ch++) {
        size_t off = ((size_t)(b * 3 + ch) * HH + y) * WW + x0;
        float4 nv = __ldcs((const float4*)(noise + off));
        float4 zv = *(const float4*)(g_Z + ((size_t)ch * HH + y) * WW + x0);
        float4 rv = *(const float4*)(&sres[ch][x0]);
        float4 ov;
        ov.x = rv.x * av.x + zv.x + kn * nv.x;
        ov.y = rv.y * av.y + zv.y + kn * nv.y;
        ov.z = rv.z * av.z + zv.z + kn * nv.z;
        ov.w = rv.w * av.w + zv.w + kn * nv.w;
        __stcs((float4*)(out + off), ov);
    }
}

// ---------------------------------------------------------------------------
extern "C" void kernel_launch(void* const* d_in, const int* in_sizes, int n_in,
                              void* d_out, int out_size) {
    const float* image    = (const float*)d_in[0];
    const float* dst_off  = (const float*)d_in[1];
    const float* ab       = (const float*)d_in[2];
    const float* centers  = (const float*)d_in[3];
    const float* noise    = (const float*)d_in[4];
    const int*   c        = (const int*)d_in[5];
    const int*   direction= (const int*)d_in[6];
    const int*   light_xy = (const int*)d_in[7];
    const int*   theta    = (const int*)d_in[8];
    float* out = (float*)d_out;

    setup_kernel<<<(HH * WW) / 256 + 1, 256>>>(dst_off, ab, centers, c,
                                               direction, light_xy, theta);
    dim3 grid(1, HH, BN);
    main_kernel<<<grid, 128>>>(image, noise, out);
}